// round 15
// baseline (speedup 1.0000x reference)
#include <cuda_runtime.h>

// ---------------------------------------------------------------------------
// Problem constants
// ---------------------------------------------------------------------------
constexpr int BB = 4;      // batch
constexpr int SS = 2048;   // sequence
constexpr int EE = 1024;   // embed
constexpr int HH = 16;     // heads
constexpr int DH = 64;     // head dim
constexpr float EPSF = 1e-5f;
constexpr int MROWS = BB * SS;           // 8192

// ---------------------------------------------------------------------------
// Scratch buffers (static device globals — no allocation anywhere)
// ---------------------------------------------------------------------------
__device__ float g_q   [(size_t)BB * SS * EE];
__device__ float g_k   [(size_t)BB * SS * EE];
__device__ float g_v   [(size_t)BB * SS * EE];
__device__ float g_attn[(size_t)BB * SS * EE];
__device__ float g_proj[(size_t)BB * SS * EE];
__device__ float g_h   [(size_t)BB * SS * EE];
__device__ float g_ff  [(size_t)BB * SS * 2 * EE];
__device__ float g_f2  [(size_t)BB * SS * EE];

// ---------------------------------------------------------------------------
// SGEMM:  C[M,N] = A[M,K] @ W[N,K]^T + bias[N]   (optional ReLU)
// Block tile 128x128, K-tile 16, 256 threads, 8x8 per-thread micro-tile.
// All dims divide tiles exactly for this problem (M=8192, N/K in {1024,2048}).
// ---------------------------------------------------------------------------
template <bool RELU>
__global__ __launch_bounds__(256) void sgemm_bias(
    const float* __restrict__ A, const float* __restrict__ W,
    const float* __restrict__ bias, float* __restrict__ C,
    int N, int K)
{
    __shared__ __align__(16) float As[16][128];
    __shared__ __align__(16) float Bs[16][128];

    const int bm = blockIdx.y;
    const int bn = blockIdx.x;
    const int tid = threadIdx.x;
    const int tx = tid & 15;      // 0..15  -> 8 output cols each
    const int ty = tid >> 4;      // 0..15  -> 8 output rows each

    const int aRow0 = bm * 128;
    const int bRow0 = bn * 128;

    // load assignment: 128 rows x 4 float4 per row = 512 float4; 2 per thread
    const int lrow = tid >> 2;              // 0..63
    const int lc4  = (tid & 3) << 2;        // 0,4,8,12

    float acc[8][8];
#pragma unroll
    for (int i = 0; i < 8; i++)
#pragma unroll
        for (int j = 0; j < 8; j++) acc[i][j] = 0.f;

    for (int kt = 0; kt < K; kt += 16) {
        // global loads first (overlap with previous tile's compute)
        const float4 fa0 = *(const float4*)(A + (size_t)(aRow0 + lrow)      * K + kt + lc4);
        const float4 fa1 = *(const float4*)(A + (size_t)(aRow0 + lrow + 64) * K + kt + lc4);
        const float4 fb0 = *(const float4*)(W + (size_t)(bRow0 + lrow)      * K + kt + lc4);
        const float4 fb1 = *(const float4*)(W + (size_t)(bRow0 + lrow + 64) * K + kt + lc4);

        __syncthreads();   // previous compute done before smem overwrite
        As[lc4 + 0][lrow]      = fa0.x;  As[lc4 + 1][lrow]      = fa0.y;
        As[lc4 + 2][lrow]      = fa0.z;  As[lc4 + 3][lrow]      = fa0.w;
        As[lc4 + 0][lrow + 64] = fa1.x;  As[lc4 + 1][lrow + 64] = fa1.y;
        As[lc4 + 2][lrow + 64] = fa1.z;  As[lc4 + 3][lrow + 64] = fa1.w;
        Bs[lc4 + 0][lrow]      = fb0.x;  Bs[lc4 + 1][lrow]      = fb0.y;
        Bs[lc4 + 2][lrow]      = fb0.z;  Bs[lc4 + 3][lrow]      = fb0.w;
        Bs[lc4 + 0][lrow + 64] = fb1.x;  Bs[lc4 + 1][lrow + 64] = fb1.y;
        Bs[lc4 + 2][lrow + 64] = fb1.z;  Bs[lc4 + 3][lrow + 64] = fb1.w;
        __syncthreads();

#pragma unroll
        for (int kk = 0; kk < 16; kk++) {
            float a[8], bfr[8];
            *(float4*)&a[0]   = *(const float4*)&As[kk][ty * 8];
            *(float4*)&a[4]   = *(const float4*)&As[kk][ty * 8 + 4];
            *(float4*)&bfr[0] = *(const float4*)&Bs[kk][tx * 8];
            *(float4*)&bfr[4] = *(const float4*)&Bs[kk][tx * 8 + 4];
#pragma unroll
            for (int i = 0; i < 8; i++)
#pragma unroll
                for (int j = 0; j < 8; j++)
                    acc[i][j] += a[i] * bfr[j];
        }
    }

    // epilogue: bias (+ReLU), vectorized stores
    const int cRow0 = bm * 128 + ty * 8;
    const int cCol0 = bn * 128 + tx * 8;
    float bi[8];
    *(float4*)&bi[0] = *(const float4*)(bias + cCol0);
    *(float4*)&bi[4] = *(const float4*)(bias + cCol0 + 4);

#pragma unroll
    for (int i = 0; i < 8; i++) {
        float r[8];
#pragma unroll
        for (int j = 0; j < 8; j++) {
            float vv = acc[i][j] + bi[j];
            if (RELU) vv = fmaxf(vv, 0.f);
            r[j] = vv;
        }
        float* cp = C + (size_t)(cRow0 + i) * N + cCol0;
        *(float4*)(cp)     = *(float4*)&r[0];
        *(float4*)(cp + 4) = *(float4*)&r[4];
    }
}

// ---------------------------------------------------------------------------
// Flash attention (fp32, exact): per block = (q-tile of 64 rows, head, batch).
// Iterates 64-key tiles with online softmax. Dh = 64.
// Thread map: 256 threads, ty=tid/16 (4 rows each), tx=tid%16 (4 cols each).
// ---------------------------------------------------------------------------
constexpr int APAD = 68;   // padded row stride (floats) for smem tiles

__global__ __launch_bounds__(256) void flash_attn(
    const float* __restrict__ q, const float* __restrict__ k,
    const float* __restrict__ v, float* __restrict__ o)
{
    extern __shared__ float sm[];
    float (*Qs)[APAD] = (float (*)[APAD])(sm);
    float (*Ks)[APAD] = (float (*)[APAD])(sm + 1 * 64 * APAD);
    float (*Vs)[APAD] = (float (*)[APAD])(sm + 2 * 64 * APAD);
    float (*Ps)[APAD] = (float (*)[APAD])(sm + 3 * 64 * APAD);

    const int b  = blockIdx.z;
    const int h  = blockIdx.y;
    const int qt = blockIdx.x;
    const int tid = threadIdx.x;
    const int tx = tid & 15;
    const int ty = tid >> 4;

    const size_t baseQ = ((size_t)(b * SS + qt * 64)) * EE + h * DH;

    // load Q tile (64 x 64): 1024 float4, 4 per thread
#pragma unroll
    for (int r = 0; r < 4; r++) {
        int vv  = tid + 256 * r;
        int row = vv >> 4;
        int c4  = (vv & 15) << 2;
        *(float4*)&Qs[row][c4] = *(const float4*)(q + baseQ + (size_t)row * EE + c4);
    }

    float m[4], l[4], oacc[4][4];
#pragma unroll
    for (int i = 0; i < 4; i++) {
        m[i] = -1e30f; l[i] = 0.f;
#pragma unroll
        for (int j = 0; j < 4; j++) oacc[i][j] = 0.f;
    }
    const float scale = 0.125f;   // 1/sqrt(64)

    for (int kt = 0; kt < SS; kt += 64) {
        const size_t baseK = ((size_t)(b * SS + kt)) * EE + h * DH;

        // stage K/V through registers (overlap global latency with prior PV)
        float4 tK[4], tV[4];
#pragma unroll
        for (int r = 0; r < 4; r++) {
            int vv  = tid + 256 * r;
            int row = vv >> 4;
            int c4  = (vv & 15) << 2;
            tK[r] = *(const float4*)(k + baseK + (size_t)row * EE + c4);
            tV[r] = *(const float4*)(v + baseK + (size_t)row * EE + c4);
        }
        __syncthreads();   // previous PV done before overwriting Ks/Vs
#pragma unroll
        for (int r = 0; r < 4; r++) {
            int vv  = tid + 256 * r;
            int row = vv >> 4;
            int c4  = (vv & 15) << 2;
            *(float4*)&Ks[row][c4] = tK[r];
            *(float4*)&Vs[row][c4] = tV[r];
        }
        __syncthreads();

        // S = Q K^T  (64x64, 4x4 per thread)
        float sacc[4][4];
#pragma unroll
        for (int i = 0; i < 4; i++)
#pragma unroll
            for (int j = 0; j < 4; j++) sacc[i][j] = 0.f;

#pragma unroll
        for (int k4 = 0; k4 < 16; k4++) {
            float4 qa[4], kb[4];
#pragma unroll
            for (int i = 0; i < 4; i++) qa[i] = *(const float4*)&Qs[ty * 4 + i][k4 * 4];
#pragma unroll
            for (int j = 0; j < 4; j++) kb[j] = *(const float4*)&Ks[tx * 4 + j][k4 * 4];
#pragma unroll
            for (int i = 0; i < 4; i++)
#pragma unroll
                for (int j = 0; j < 4; j++)
                    sacc[i][j] += qa[i].x * kb[j].x + qa[i].y * kb[j].y +
                                  qa[i].z * kb[j].z + qa[i].w * kb[j].w;
        }

        // online softmax update per row (row owned by 16 threads across tx)
#pragma unroll
        for (int i = 0; i < 4; i++) {
            float rm = -1e30f;
#pragma unroll
            for (int j = 0; j < 4; j++) {
                sacc[i][j] *= scale;
                rm = fmaxf(rm, sacc[i][j]);
            }
#pragma unroll
            for (int off = 1; off < 16; off <<= 1)
                rm = fmaxf(rm, __shfl_xor_sync(0xffffffffu, rm, off, 16));

            const float mn = fmaxf(m[i], rm);
            const float f  = __expf(m[i] - mn);
            float rs = 0.f;
#pragma unroll
            for (int j = 0; j < 4; j++) {
                float p = __expf(sacc[i][j] - mn);
                sacc[i][j] = p;
                rs += p;
            }
#pragma unroll
            for (int off = 1; off < 16; off <<= 1)
                rs += __shfl_xor_sync(0xffffffffu, rs, off, 16);

            l[i] = l[i] * f + rs;
            m[i] = mn;
#pragma unroll
            for (int j = 0; j < 4; j++) oacc[i][j] *= f;

            *(float4*)&Ps[ty * 4 + i][tx * 4] =
                make_float4(sacc[i][0], sacc[i][1], sacc[i][2], sacc[i][3]);
        }
        __syncthreads();

        // O += P @ V   (64x64 * 64x64, 4x4 per thread)
#pragma unroll
        for (int c4 = 0; c4 < 16; c4++) {
            float4 pf[4], vf[4];
#pragma unroll
            for (int i = 0; i < 4; i++)  pf[i] = *(const float4*)&Ps[ty * 4 + i][c4 * 4];
#pragma unroll
            for (int cc = 0; cc < 4; cc++) vf[cc] = *(const float4*)&Vs[c4 * 4 + cc][tx * 4];
#pragma unroll
            for (int i = 0; i < 4; i++) {
                oacc[i][0] += pf[i].x * vf[0].x + pf[i].y * vf[1].x + pf[i].z * vf[2].x + pf[i].w * vf[3].x;
                oacc[i][1] += pf[i].x * vf[0].y + pf[i].y * vf[1].y + pf[i].z * vf[2].y + pf[i].w * vf[3].y;
                oacc[i][2] += pf[i].x * vf[0].z + pf[i].y * vf[1].z + pf[i].z * vf[2].z + pf[i].w * vf[3].z;
                oacc[i][3] += pf[i].x * vf[0].w + pf[i].y * vf[1].w + pf[i].z * vf[2].w + pf[i].w * vf[3].w;
            }
        }
    }

    // normalize and write out (layout identical to (B,S,E) reshape)
#pragma unroll
    for (int i = 0; i < 4; i++) {
        const float inv = 1.f / l[i];
        float4 r = make_float4(oacc[i][0] * inv, oacc[i][1] * inv,
                               oacc[i][2] * inv, oacc[i][3] * inv);
        *(float4*)(o + baseQ + (size_t)(ty * 4 + i) * EE + tx * 4) = r;
    }
}

// ---------------------------------------------------------------------------
// Residual add + adaptive norm: out = a[s] * normalize(X+R over E) + b[s]
// One block per (b,s) row; 256 threads x 4 floats = E = 1024.
// ---------------------------------------------------------------------------
__global__ __launch_bounds__(256) void addnorm_kernel(
    const float* __restrict__ X, const float* __restrict__ R,
    const float* __restrict__ ga, const float* __restrict__ gb,
    float* __restrict__ out)
{
    __shared__ float red[18];
    const int row = blockIdx.x;
    const int s   = row & (SS - 1);
    const size_t base = (size_t)row * EE;
    const int tid = threadIdx.x;

    const float4 xv = *(const float4*)(X + base + tid * 4);
    const float4 rv = *(const float4*)(R + base + tid * 4);
    float4 vv = make_float4(xv.x + rv.x, xv.y + rv.y, xv.z + rv.z, xv.w + rv.w);

    float sum = vv.x + vv.y + vv.z + vv.w;
    float sq  = vv.x * vv.x + vv.y * vv.y + vv.z * vv.z + vv.w * vv.w;
#pragma unroll
    for (int off = 16; off > 0; off >>= 1) {
        sum += __shfl_xor_sync(0xffffffffu, sum, off);
        sq  += __shfl_xor_sync(0xffffffffu, sq,  off);
    }
    const int warp = tid >> 5, lane = tid & 31;
    if (lane == 0) { red[warp] = sum; red[warp + 8] = sq; }
    __syncthreads();
    if (tid == 0) {
        float s1 = 0.f, s2 = 0.f;
#pragma unroll
        for (int i = 0; i < 8; i++) { s1 += red[i]; s2 += red[i + 8]; }
        const float mean = s1 * (1.f / EE);
        const float var  = s2 * (1.f / EE) - mean * mean;
        red[16] = mean;
        red[17] = rsqrtf(var + EPSF);
    }
    __syncthreads();
    const float mean = red[16];
    const float inv  = red[17];
    const float aa = ga[s];
    const float bb = gb[s];

    float4 r = make_float4(aa * (vv.x - mean) * inv + bb,
                           aa * (vv.y - mean) * inv + bb,
                           aa * (vv.z - mean) * inv + bb,
                           aa * (vv.w - mean) * inv + bb);
    *(float4*)(out + base + tid * 4) = r;
}

// ---------------------------------------------------------------------------
// Launch
// ---------------------------------------------------------------------------
extern "C" void kernel_launch(void* const* d_in, const int* in_sizes, int n_in,
                              void* d_out, int out_size)
{
    (void)in_sizes; (void)n_in; (void)out_size;

    const float* x   = (const float*)d_in[0];
    const float* Wq  = (const float*)d_in[1];
    const float* bq  = (const float*)d_in[2];
    const float* Wk  = (const float*)d_in[3];
    const float* bk  = (const float*)d_in[4];
    const float* Wv  = (const float*)d_in[5];
    const float* bv  = (const float*)d_in[6];
    const float* Wo  = (const float*)d_in[7];
    const float* bo  = (const float*)d_in[8];
    const float* a1  = (const float*)d_in[9];
    const float* b1n = (const float*)d_in[10];
    const float* W1  = (const float*)d_in[11];
    const float* b1  = (const float*)d_in[12];
    const float* W2  = (const float*)d_in[13];
    const float* b2  = (const float*)d_in[14];
    const float* a2  = (const float*)d_in[15];
    const float* b2n = (const float*)d_in[16];
    float* out = (float*)d_out;

    float *gq, *gk, *gv, *gattn, *gproj, *gh, *gff, *gf2;
    cudaGetSymbolAddress((void**)&gq,    g_q);
    cudaGetSymbolAddress((void**)&gk,    g_k);
    cudaGetSymbolAddress((void**)&gv,    g_v);
    cudaGetSymbolAddress((void**)&gattn, g_attn);
    cudaGetSymbolAddress((void**)&gproj, g_proj);
    cudaGetSymbolAddress((void**)&gh,    g_h);
    cudaGetSymbolAddress((void**)&gff,   g_ff);
    cudaGetSymbolAddress((void**)&gf2,   g_f2);

    const dim3 gridE (EE / 128,     MROWS / 128);   // (8, 64)
    const dim3 grid2E(2 * EE / 128, MROWS / 128);   // (16, 64)

    // QKV projections
    sgemm_bias<false><<<gridE, 256>>>(x, Wq, bq, gq, EE, EE);
    sgemm_bias<false><<<gridE, 256>>>(x, Wk, bk, gk, EE, EE);
    sgemm_bias<false><<<gridE, 256>>>(x, Wv, bv, gv, EE, EE);

    // attention
    const int shmem = 4 * 64 * APAD * (int)sizeof(float);   // 69,632 B
    cudaFuncSetAttribute(flash_attn, cudaFuncAttributeMaxDynamicSharedMemorySize, shmem);
    flash_attn<<<dim3(SS / 64, HH, BB), 256, shmem>>>(gq, gk, gv, gattn);

    // output projection + norm1
    sgemm_bias<false><<<gridE, 256>>>(gattn, Wo, bo, gproj, EE, EE);
    addnorm_kernel<<<MROWS, 256>>>(gproj, x, a1, b1n, gh);

    // FFN + norm2
    sgemm_bias<true ><<<grid2E, 256>>>(gh, W1, b1, gff, 2 * EE, EE);
    sgemm_bias<false><<<gridE,  256>>>(gff, W2, b2, gf2, EE, 2 * EE);
    addnorm_kernel<<<MROWS, 256>>>(gf2, gh, a2, b2n, out);
}

// round 16
// speedup vs baseline: 1.0011x; 1.0011x over previous
#include <cuda_runtime.h>

// ---------------------------------------------------------------------------
// Problem constants
// ---------------------------------------------------------------------------
constexpr int BB = 4;      // batch
constexpr int SS = 2048;   // sequence
constexpr int EE = 1024;   // embed
constexpr int HH = 16;     // heads
constexpr int DH = 64;     // head dim
constexpr float EPSF = 1e-5f;
constexpr int MROWS = BB * SS;           // 8192

// ---------------------------------------------------------------------------
// Scratch buffers (static device globals — no allocation anywhere)
// ---------------------------------------------------------------------------
__device__ float g_q   [(size_t)BB * SS * EE];
__device__ float g_k   [(size_t)BB * SS * EE];
__device__ float g_v   [(size_t)BB * SS * EE];
__device__ float g_attn[(size_t)BB * SS * EE];
__device__ float g_proj[(size_t)BB * SS * EE];
__device__ float g_h   [(size_t)BB * SS * EE];
__device__ float g_ff  [(size_t)BB * SS * 2 * EE];
__device__ float g_f2  [(size_t)BB * SS * EE];

// ---------------------------------------------------------------------------
// SGEMM:  C[M,N] = A[M,K] @ W[N,K]^T + bias[N]   (optional ReLU)
// Block tile 128x128, K-tile 16, 256 threads, 8x8 per-thread micro-tile.
// All dims divide tiles exactly for this problem (M=8192, N/K in {1024,2048}).
// ---------------------------------------------------------------------------
template <bool RELU>
__global__ __launch_bounds__(256) void sgemm_bias(
    const float* __restrict__ A, const float* __restrict__ W,
    const float* __restrict__ bias, float* __restrict__ C,
    int N, int K)
{
    __shared__ __align__(16) float As[16][128];
    __shared__ __align__(16) float Bs[16][128];

    const int bm = blockIdx.y;
    const int bn = blockIdx.x;
    const int tid = threadIdx.x;
    const int tx = tid & 15;      // 0..15  -> 8 output cols each
    const int ty = tid >> 4;      // 0..15  -> 8 output rows each

    const int aRow0 = bm * 128;
    const int bRow0 = bn * 128;

    // load assignment: 128 rows x 4 float4 per row = 512 float4; 2 per thread
    const int lrow = tid >> 2;              // 0..63
    const int lc4  = (tid & 3) << 2;        // 0,4,8,12

    float acc[8][8];
#pragma unroll
    for (int i = 0; i < 8; i++)
#pragma unroll
        for (int j = 0; j < 8; j++) acc[i][j] = 0.f;

    for (int kt = 0; kt < K; kt += 16) {
        // global loads first (overlap with previous tile's compute)
        const float4 fa0 = *(const float4*)(A + (size_t)(aRow0 + lrow)      * K + kt + lc4);
        const float4 fa1 = *(const float4*)(A + (size_t)(aRow0 + lrow + 64) * K + kt + lc4);
        const float4 fb0 = *(const float4*)(W + (size_t)(bRow0 + lrow)      * K + kt + lc4);
        const float4 fb1 = *(const float4*)(W + (size_t)(bRow0 + lrow + 64) * K + kt + lc4);

        __syncthreads();   // previous compute done before smem overwrite
        As[lc4 + 0][lrow]      = fa0.x;  As[lc4 + 1][lrow]      = fa0.y;
        As[lc4 + 2][lrow]      = fa0.z;  As[lc4 + 3][lrow]      = fa0.w;
        As[lc4 + 0][lrow + 64] = fa1.x;  As[lc4 + 1][lrow + 64] = fa1.y;
        As[lc4 + 2][lrow + 64] = fa1.z;  As[lc4 + 3][lrow + 64] = fa1.w;
        Bs[lc4 + 0][lrow]      = fb0.x;  Bs[lc4 + 1][lrow]      = fb0.y;
        Bs[lc4 + 2][lrow]      = fb0.z;  Bs[lc4 + 3][lrow]      = fb0.w;
        Bs[lc4 + 0][lrow + 64] = fb1.x;  Bs[lc4 + 1][lrow + 64] = fb1.y;
        Bs[lc4 + 2][lrow + 64] = fb1.z;  Bs[lc4 + 3][lrow + 64] = fb1.w;
        __syncthreads();

#pragma unroll
        for (int kk = 0; kk < 16; kk++) {
            float a[8], bfr[8];
            *(float4*)&a[0]   = *(const float4*)&As[kk][ty * 8];
            *(float4*)&a[4]   = *(const float4*)&As[kk][ty * 8 + 4];
            *(float4*)&bfr[0] = *(const float4*)&Bs[kk][tx * 8];
            *(float4*)&bfr[4] = *(const float4*)&Bs[kk][tx * 8 + 4];
#pragma unroll
            for (int i = 0; i < 8; i++)
#pragma unroll
                for (int j = 0; j < 8; j++)
                    acc[i][j] += a[i] * bfr[j];
        }
    }

    // epilogue: bias (+ReLU), vectorized stores
    const int cRow0 = bm * 128 + ty * 8;
    const int cCol0 = bn * 128 + tx * 8;
    float bi[8];
    *(float4*)&bi[0] = *(const float4*)(bias + cCol0);
    *(float4*)&bi[4] = *(const float4*)(bias + cCol0 + 4);

#pragma unroll
    for (int i = 0; i < 8; i++) {
        float r[8];
#pragma unroll
        for (int j = 0; j < 8; j++) {
            float vv = acc[i][j] + bi[j];
            if (RELU) vv = fmaxf(vv, 0.f);
            r[j] = vv;
        }
        float* cp = C + (size_t)(cRow0 + i) * N + cCol0;
        *(float4*)(cp)     = *(float4*)&r[0];
        *(float4*)(cp + 4) = *(float4*)&r[4];
    }
}

// ---------------------------------------------------------------------------
// Flash attention (fp32, exact): per block = (q-tile of 64 rows, head, batch).
// Iterates 64-key tiles with online softmax. Dh = 64.
// Thread map: 256 threads, ty=tid/16 (4 rows each), tx=tid%16 (4 cols each).
// ---------------------------------------------------------------------------
constexpr int APAD = 68;   // padded row stride (floats) for smem tiles

__global__ __launch_bounds__(256) void flash_attn(
    const float* __restrict__ q, const float* __restrict__ k,
    const float* __restrict__ v, float* __restrict__ o)
{
    extern __shared__ float sm[];
    float (*Qs)[APAD] = (float (*)[APAD])(sm);
    float (*Ks)[APAD] = (float (*)[APAD])(sm + 1 * 64 * APAD);
    float (*Vs)[APAD] = (float (*)[APAD])(sm + 2 * 64 * APAD);
    float (*Ps)[APAD] = (float (*)[APAD])(sm + 3 * 64 * APAD);

    const int b  = blockIdx.z;
    const int h  = blockIdx.y;
    const int qt = blockIdx.x;
    const int tid = threadIdx.x;
    const int tx = tid & 15;
    const int ty = tid >> 4;

    const size_t baseQ = ((size_t)(b * SS + qt * 64)) * EE + h * DH;

    // load Q tile (64 x 64): 1024 float4, 4 per thread
#pragma unroll
    for (int r = 0; r < 4; r++) {
        int vv  = tid + 256 * r;
        int row = vv >> 4;
        int c4  = (vv & 15) << 2;
        *(float4*)&Qs[row][c4] = *(const float4*)(q + baseQ + (size_t)row * EE + c4);
    }

    float m[4], l[4], oacc[4][4];
#pragma unroll
    for (int i = 0; i < 4; i++) {
        m[i] = -1e30f; l[i] = 0.f;
#pragma unroll
        for (int j = 0; j < 4; j++) oacc[i][j] = 0.f;
    }
    const float scale = 0.125f;   // 1/sqrt(64)

    for (int kt = 0; kt < SS; kt += 64) {
        const size_t baseK = ((size_t)(b * SS + kt)) * EE + h * DH;

        // stage K/V through registers (overlap global latency with prior PV)
        float4 tK[4], tV[4];
#pragma unroll
        for (int r = 0; r < 4; r++) {
            int vv  = tid + 256 * r;
            int row = vv >> 4;
            int c4  = (vv & 15) << 2;
            tK[r] = *(const float4*)(k + baseK + (size_t)row * EE + c4);
            tV[r] = *(const float4*)(v + baseK + (size_t)row * EE + c4);
        }
        __syncthreads();   // previous PV done before overwriting Ks/Vs
#pragma unroll
        for (int r = 0; r < 4; r++) {
            int vv  = tid + 256 * r;
            int row = vv >> 4;
            int c4  = (vv & 15) << 2;
            *(float4*)&Ks[row][c4] = tK[r];
            *(float4*)&Vs[row][c4] = tV[r];
        }
        __syncthreads();

        // S = Q K^T  (64x64, 4x4 per thread)
        float sacc[4][4];
#pragma unroll
        for (int i = 0; i < 4; i++)
#pragma unroll
            for (int j = 0; j < 4; j++) sacc[i][j] = 0.f;

#pragma unroll
        for (int k4 = 0; k4 < 16; k4++) {
            float4 qa[4], kb[4];
#pragma unroll
            for (int i = 0; i < 4; i++) qa[i] = *(const float4*)&Qs[ty * 4 + i][k4 * 4];
#pragma unroll
            for (int j = 0; j < 4; j++) kb[j] = *(const float4*)&Ks[tx * 4 + j][k4 * 4];
#pragma unroll
            for (int i = 0; i < 4; i++)
#pragma unroll
                for (int j = 0; j < 4; j++)
                    sacc[i][j] += qa[i].x * kb[j].x + qa[i].y * kb[j].y +
                                  qa[i].z * kb[j].z + qa[i].w * kb[j].w;
        }

        // online softmax update per row (row owned by 16 threads across tx)
#pragma unroll
        for (int i = 0; i < 4; i++) {
            float rm = -1e30f;
#pragma unroll
            for (int j = 0; j < 4; j++) {
                sacc[i][j] *= scale;
                rm = fmaxf(rm, sacc[i][j]);
            }
#pragma unroll
            for (int off = 1; off < 16; off <<= 1)
                rm = fmaxf(rm, __shfl_xor_sync(0xffffffffu, rm, off, 16));

            const float mn = fmaxf(m[i], rm);
            const float f  = __expf(m[i] - mn);
            float rs = 0.f;
#pragma unroll
            for (int j = 0; j < 4; j++) {
                float p = __expf(sacc[i][j] - mn);
                sacc[i][j] = p;
                rs += p;
            }
#pragma unroll
            for (int off = 1; off < 16; off <<= 1)
                rs += __shfl_xor_sync(0xffffffffu, rs, off, 16);

            l[i] = l[i] * f + rs;
            m[i] = mn;
#pragma unroll
            for (int j = 0; j < 4; j++) oacc[i][j] *= f;

            *(float4*)&Ps[ty * 4 + i][tx * 4] =
                make_float4(sacc[i][0], sacc[i][1], sacc[i][2], sacc[i][3]);
        }
        __syncthreads();

        // O += P @ V   (64x64 * 64x64, 4x4 per thread)
#pragma unroll
        for (int c4 = 0; c4 < 16; c4++) {
            float4 pf[4], vf[4];
#pragma unroll
            for (int i = 0; i < 4; i++)  pf[i] = *(const float4*)&Ps[ty * 4 + i][c4 * 4];
#pragma unroll
            for (int cc = 0; cc < 4; cc++) vf[cc] = *(const float4*)&Vs[c4 * 4 + cc][tx * 4];
#pragma unroll
            for (int i = 0; i < 4; i++) {
                oacc[i][0] += pf[i].x * vf[0].x + pf[i].y * vf[1].x + pf[i].z * vf[2].x + pf[i].w * vf[3].x;
                oacc[i][1] += pf[i].x * vf[0].y + pf[i].y * vf[1].y + pf[i].z * vf[2].y + pf[i].w * vf[3].y;
                oacc[i][2] += pf[i].x * vf[0].z + pf[i].y * vf[1].z + pf[i].z * vf[2].z + pf[i].w * vf[3].z;
                oacc[i][3] += pf[i].x * vf[0].w + pf[i].y * vf[1].w + pf[i].z * vf[2].w + pf[i].w * vf[3].w;
            }
        }
    }

    // normalize and write out (layout identical to (B,S,E) reshape)
#pragma unroll
    for (int i = 0; i < 4; i++) {
        const float inv = 1.f / l[i];
        float4 r = make_float4(oacc[i][0] * inv, oacc[i][1] * inv,
                               oacc[i][2] * inv, oacc[i][3] * inv);
        *(float4*)(o + baseQ + (size_t)(ty * 4 + i) * EE + tx * 4) = r;
    }
}

// ---------------------------------------------------------------------------
// Residual add + adaptive norm: out = a[s] * normalize(X+R over E) + b[s]
// One block per (b,s) row; 256 threads x 4 floats = E = 1024.
// ---------------------------------------------------------------------------
__global__ __launch_bounds__(256) void addnorm_kernel(
    const float* __restrict__ X, const float* __restrict__ R,
    const float* __restrict__ ga, const float* __restrict__ gb,
    float* __restrict__ out)
{
    __shared__ float red[18];
    const int row = blockIdx.x;
    const int s   = row & (SS - 1);
    const size_t base = (size_t)row * EE;
    const int tid = threadIdx.x;

    const float4 xv = *(const float4*)(X + base + tid * 4);
    const float4 rv = *(const float4*)(R + base + tid * 4);
    float4 vv = make_float4(xv.x + rv.x, xv.y + rv.y, xv.z + rv.z, xv.w + rv.w);

    float sum = vv.x + vv.y + vv.z + vv.w;
    float sq  = vv.x * vv.x + vv.y * vv.y + vv.z * vv.z + vv.w * vv.w;
#pragma unroll
    for (int off = 16; off > 0; off >>= 1) {
        sum += __shfl_xor_sync(0xffffffffu, sum, off);
        sq  += __shfl_xor_sync(0xffffffffu, sq,  off);
    }
    const int warp = tid >> 5, lane = tid & 31;
    if (lane == 0) { red[warp] = sum; red[warp + 8] = sq; }
    __syncthreads();
    if (tid == 0) {
        float s1 = 0.f, s2 = 0.f;
#pragma unroll
        for (int i = 0; i < 8; i++) { s1 += red[i]; s2 += red[i + 8]; }
        const float mean = s1 * (1.f / EE);
        const float var  = s2 * (1.f / EE) - mean * mean;
        red[16] = mean;
        red[17] = rsqrtf(var + EPSF);
    }
    __syncthreads();
    const float mean = red[16];
    const float inv  = red[17];
    const float aa = ga[s];
    const float bb = gb[s];

    float4 r = make_float4(aa * (vv.x - mean) * inv + bb,
                           aa * (vv.y - mean) * inv + bb,
                           aa * (vv.z - mean) * inv + bb,
                           aa * (vv.w - mean) * inv + bb);
    *(float4*)(out + base + tid * 4) = r;
}

// ---------------------------------------------------------------------------
// Launch
// ---------------------------------------------------------------------------
extern "C" void kernel_launch(void* const* d_in, const int* in_sizes, int n_in,
                              void* d_out, int out_size)
{
    (void)in_sizes; (void)n_in; (void)out_size;

    const float* x   = (const float*)d_in[0];
    const float* Wq  = (const float*)d_in[1];
    const float* bq  = (const float*)d_in[2];
    const float* Wk  = (const float*)d_in[3];
    const float* bk  = (const float*)d_in[4];
    const float* Wv  = (const float*)d_in[5];
    const float* bv  = (const float*)d_in[6];
    const float* Wo  = (const float*)d_in[7];
    const float* bo  = (const float*)d_in[8];
    const float* a1  = (const float*)d_in[9];
    const float* b1n = (const float*)d_in[10];
    const float* W1  = (const float*)d_in[11];
    const float* b1  = (const float*)d_in[12];
    const float* W2  = (const float*)d_in[13];
    const float* b2  = (const float*)d_in[14];
    const float* a2  = (const float*)d_in[15];
    const float* b2n = (const float*)d_in[16];
    float* out = (float*)d_out;

    float *gq, *gk, *gv, *gattn, *gproj, *gh, *gff, *gf2;
    cudaGetSymbolAddress((void**)&gq,    g_q);
    cudaGetSymbolAddress((void**)&gk,    g_k);
    cudaGetSymbolAddress((void**)&gv,    g_v);
    cudaGetSymbolAddress((void**)&gattn, g_attn);
    cudaGetSymbolAddress((void**)&gproj, g_proj);
    cudaGetSymbolAddress((void**)&gh,    g_h);
    cudaGetSymbolAddress((void**)&gff,   g_ff);
    cudaGetSymbolAddress((void**)&gf2,   g_f2);

    const dim3 gridE (EE / 128,     MROWS / 128);   // (8, 64)
    const dim3 grid2E(2 * EE / 128, MROWS / 128);   // (16, 64)

    // QKV projections
    sgemm_bias<false><<<gridE, 256>>>(x, Wq, bq, gq, EE, EE);
    sgemm_bias<false><<<gridE, 256>>>(x, Wk, bk, gk, EE, EE);
    sgemm_bias<false><<<gridE, 256>>>(x, Wv, bv, gv, EE, EE);

    // attention
    const int shmem = 4 * 64 * APAD * (int)sizeof(float);   // 69,632 B
    cudaFuncSetAttribute(flash_attn, cudaFuncAttributeMaxDynamicSharedMemorySize, shmem);
    flash_attn<<<dim3(SS / 64, HH, BB), 256, shmem>>>(gq, gk, gv, gattn);

    // output projection + norm1
    sgemm_bias<false><<<gridE, 256>>>(gattn, Wo, bo, gproj, EE, EE);
    addnorm_kernel<<<MROWS, 256>>>(gproj, x, a1, b1n, gh);

    // FFN + norm2
    sgemm_bias<true ><<<grid2E, 256>>>(gh, W1, b1, gff, 2 * EE, EE);
    sgemm_bias<false><<<gridE,  256>>>(gff, W2, b2, gf2, EE, 2 * EE);
    addnorm_kernel<<<MROWS, 256>>>(gf2, gh, a2, b2n, out);
}